// round 11
// baseline (speedup 1.0000x reference)
#include <cuda_runtime.h>
#include <math.h>

#define NUM_E   100000
#define HDIM    200
#define H4      50          // HDIM / 4
#define NEDGE   1000000
#define BATCH   512
#define RRELU_SLOPE 0.2291666666666667f
#define BN_EPS  1e-5f

#define AGG_OFF ((long long)NUM_E * HDIM)   // agg/h2 region starts at out + 20M floats

// ---------------- tiny device globals ONLY (~1.21 MB; no static ctor) ----------------
__device__ float g_deg  [NUM_E];
__device__ float g_gate [NUM_E];
__device__ float g_q    [BATCH * HDIM];
__device__ float g_stats[8];
__device__ int   g_is64;

// ---------------- helpers ----------------
__device__ __forceinline__ long long ld_idx(const void* p, long long i, int is64) {
    if (is64) return ((const long long*)p)[i];
    return (long long)((const int*)p)[i];
}

__device__ __forceinline__ void red_add_v4(float* addr, float4 v) {
    asm volatile("red.global.add.v4.f32 [%0], {%1,%2,%3,%4};"
                 :: "l"(addr), "f"(v.x), "f"(v.y), "f"(v.z), "f"(v.w) : "memory");
}

__device__ __forceinline__ float warp_sum(float v) {
    #pragma unroll
    for (int o = 16; o > 0; o >>= 1) v += __shfl_xor_sync(0xffffffffu, v, o);
    return v;
}

__device__ __forceinline__ float rrelu(float x) {
    return x >= 0.0f ? x : x * RRELU_SLOPE;
}

// ---------------- index width detection (int32 vs int64) ----------------
__global__ __launch_bounds__(32) void k_detect(const unsigned int* w) {
    if (threadIdx.x == 0) {
        int is64 = 1;
        for (int i = 0; i < 64; i++) {
            if (w[2 * i + 1] != 0u) { is64 = 0; break; }
        }
        g_is64 = is64;
    }
}

// ---------------- zero kernels ----------------
__global__ __launch_bounds__(256) void k_zero_init(float* __restrict__ agg) {
    long long i = (long long)blockIdx.x * blockDim.x + threadIdx.x;
    float4 z = make_float4(0.f, 0.f, 0.f, 0.f);
    if (i < (long long)NUM_E * H4) ((float4*)agg)[i] = z;
    if (i < NUM_E / 4)             ((float4*)g_deg)[i] = z;
    if (i < 2)                     ((float4*)g_stats)[i] = z;
}

__global__ __launch_bounds__(256) void k_zero_agg(float* __restrict__ agg) {
    long long i = (long long)blockIdx.x * blockDim.x + threadIdx.x;
    if (i < (long long)NUM_E * H4)
        ((float4*)agg)[i] = make_float4(0.f, 0.f, 0.f, 0.f);
}

// ---------------- edge scatter (warp per edge): agg[dst] += h[src] + rel[etype] ----------------
__global__ __launch_bounds__(256) void k_edges(const void* srcp, const void* dstp, const void* etp,
                                               const float* __restrict__ rel_emb,
                                               const float* __restrict__ hsrc,
                                               float* __restrict__ agg, int do_deg) {
    long long w = ((long long)blockIdx.x * blockDim.x + threadIdx.x) >> 5;
    int lane = threadIdx.x & 31;
    if (w >= NEDGE) return;
    int is64 = g_is64;
    long long d = ld_idx(dstp, w, is64);
    long long t = ld_idx(etp, w, is64);
    long long s = ld_idx(srcp, w, is64);
    if (do_deg && lane == 0) atomicAdd(&g_deg[d], 1.0f);
    const float4* r4 = (const float4*)(rel_emb + t * HDIM);
    const float4* h4 = (const float4*)(hsrc + s * HDIM);
    float* agb = agg + d * HDIM;
    for (int c = lane; c < H4; c += 32) {
        float4 v = h4[c], r = r4[c];
        v.x += r.x; v.y += r.y; v.z += r.z; v.w += r.w;
        red_add_v4(agb + 4 * c, v);
    }
}

// ---------------- fused node transform: hout = rrelu((agg/max(deg,1)) @ Wn + hin @ Wl)
// 32-row tile, 400 threads, BK=8 double-buffered W (1 sync/iter, loads overlap compute).
// Microtile 4x4, merged accumulator. Dynamic smem 76.8KB -> 2 blocks/SM.
__global__ __launch_bounds__(400, 2) void k_transform(const float* __restrict__ hin,
                                                      const float* __restrict__ Wn,
                                                      const float* __restrict__ Wl,
                                                      const float* __restrict__ agg,
                                                      float* __restrict__ hout) {
    extern __shared__ float sm[];
    float* As = sm;                   // 32*200
    float* Hs = As + 32 * HDIM;       // 32*200
    float* Wb = Hs + 32 * HDIM;       // [2 buf][2 mat][8 rows][200]

    const int tid = threadIdx.x;
    const int tx = tid % 50;
    const int ty = tid / 50;          // 0..7
    const long long base = (long long)blockIdx.x * 32;

    // stage A (pre-normalized) and H tiles
    for (int i = tid; i < 32 * H4; i += 400) {
        int r = i / H4, c4 = i % H4;
        long long n = base + r;
        float inv = 1.0f / fmaxf(g_deg[n], 1.0f);
        float4 a = *(const float4*)(agg + n * HDIM + 4 * c4);
        a.x *= inv; a.y *= inv; a.z *= inv; a.w *= inv;
        *(float4*)(As + r * HDIM + 4 * c4) = a;
        *(float4*)(Hs + r * HDIM + 4 * c4) = *(const float4*)(hin + n * HDIM + 4 * c4);
    }

    // stage W k-tile kt into buffer buf: 2 mats x 8 rows x 50 float4 = 800 f4, 2 per thread
    auto stageW = [&](int kt, int buf) {
        #pragma unroll
        for (int u = 0; u < 2; ++u) {
            int i  = tid + u * 400;
            int m  = i / 400;
            int rr = (i % 400) / 50;
            int c4 = i % 50;
            const float* W = m ? Wl : Wn;
            *(float4*)(Wb + (((buf * 2 + m) * 8 + rr) * HDIM) + 4 * c4) =
                *(const float4*)(W + (kt * 8 + rr) * HDIM + 4 * c4);
        }
    };

    stageW(0, 0);
    __syncthreads();

    float acc[16];
    #pragma unroll
    for (int i = 0; i < 16; i++) acc[i] = 0.f;

    for (int kt = 0; kt < 25; ++kt) {
        const int cur = kt & 1;
        if (kt < 24) stageW(kt + 1, cur ^ 1);   // overlaps with compute below

        const float* Wn_s = Wb + (cur * 2 + 0) * 8 * HDIM;
        const float* Wl_s = Wb + (cur * 2 + 1) * 8 * HDIM;

        #pragma unroll
        for (int kq = 0; kq < 2; ++kq) {
            const int k = kt * 8 + kq * 4;
            float av[16], hv[16];
            #pragma unroll
            for (int r = 0; r < 4; ++r) {
                float4 a = *(float4*)&As[(ty * 4 + r) * HDIM + k];
                float4 h = *(float4*)&Hs[(ty * 4 + r) * HDIM + k];
                av[r * 4 + 0] = a.x; av[r * 4 + 1] = a.y; av[r * 4 + 2] = a.z; av[r * 4 + 3] = a.w;
                hv[r * 4 + 0] = h.x; hv[r * 4 + 1] = h.y; hv[r * 4 + 2] = h.z; hv[r * 4 + 3] = h.w;
            }
            #pragma unroll
            for (int j = 0; j < 4; ++j) {
                float4 wn = *(float4*)&Wn_s[(kq * 4 + j) * HDIM + 4 * tx];
                float4 wl = *(float4*)&Wl_s[(kq * 4 + j) * HDIM + 4 * tx];
                #pragma unroll
                for (int r = 0; r < 4; ++r) {
                    float a = av[r * 4 + j];
                    float h = hv[r * 4 + j];
                    acc[r * 4 + 0] += a * wn.x + h * wl.x;
                    acc[r * 4 + 1] += a * wn.y + h * wl.y;
                    acc[r * 4 + 2] += a * wn.z + h * wl.z;
                    acc[r * 4 + 3] += a * wn.w + h * wl.w;
                }
            }
        }
        __syncthreads();
    }

    #pragma unroll
    for (int r = 0; r < 4; ++r) {
        long long n = base + ty * 4 + r;
        float4 o;
        o.x = rrelu(acc[r * 4 + 0]);
        o.y = rrelu(acc[r * 4 + 1]);
        o.z = rrelu(acc[r * 4 + 2]);
        o.w = rrelu(acc[r * 4 + 3]);
        *(float4*)(hout + n * HDIM + 4 * tx) = o;
    }
}

// ---------------- gate scalar per node ----------------
__global__ __launch_bounds__(256) void k_gatepre(const float* __restrict__ theta,
                                                 const float* __restrict__ gw,
                                                 const float* __restrict__ gb) {
    long long w = ((long long)blockIdx.x * blockDim.x + threadIdx.x) >> 5;
    int lane = threadIdx.x & 31;
    if (w >= NUM_E) return;
    const float4* t4 = (const float4*)(theta + w * HDIM);
    const float4* w4 = (const float4*)gw;
    float p = 0.f;
    for (int c = lane; c < H4; c += 32) {
        float4 a = t4[c], b = w4[c];
        p += a.x * b.x + a.y * b.y + a.z * b.z + a.w * b.w;
    }
    p = warp_sum(p);
    if (lane == 0) g_gate[w] = 1.0f / (1.0f + expf(-(p + gb[0])));
}

// ---------------- blend + transpose: hT[c][n] ----------------
__global__ __launch_bounds__(256) void k_blendT(const float* __restrict__ h2,
                                                const float* __restrict__ ent,
                                                float* __restrict__ hT) {
    __shared__ float sm[32 * 201];
    const int tid = threadIdx.x;
    const long long n0 = (long long)blockIdx.x * 32;

    for (int i = tid; i < 32 * H4; i += 256) {
        int r = i / H4, c4 = i % H4;
        long long n = n0 + r;
        float g = g_gate[n], og = 1.0f - g;
        float4 h = *(const float4*)(h2 + n * HDIM + 4 * c4);
        float4 e = *(const float4*)(ent + n * HDIM + 4 * c4);
        sm[r * 201 + 4 * c4 + 0] = g * h.x + og * e.x;
        sm[r * 201 + 4 * c4 + 1] = g * h.y + og * e.y;
        sm[r * 201 + 4 * c4 + 2] = g * h.z + og * e.z;
        sm[r * 201 + 4 * c4 + 3] = g * h.w + og * e.w;
    }
    __syncthreads();

    for (int i = tid; i < HDIM * 32; i += 256) {
        int r = i & 31;
        int c = i >> 5;
        hT[(long long)c * NUM_E + n0 + r] = sm[r * 201 + c];
    }
}

// ---------------- BN batch statistics ----------------
__global__ __launch_bounds__(256) void k_bnstats(const float* __restrict__ hT,
                                                 const float* __restrict__ rel_emb,
                                                 const float* __restrict__ freq,
                                                 const void* sidx, const void* ridx) {
    int b = blockIdx.x;
    int tid = threadIdx.x;
    int lane = tid & 31;
    int is64 = g_is64;
    long long s = ld_idx(sidx, b, is64);
    long long r = ld_idx(ridx, b, is64);
    float e = 0.f, rr = 0.f, f = 0.f;
    if (tid < HDIM) {
        e  = hT[(long long)tid * NUM_E + s];
        rr = rel_emb[r * HDIM + tid];
        f  = freq[(long long)b * HDIM + tid];
    }
    float s0 = warp_sum(e),  s1 = warp_sum(e * e);
    float s2 = warp_sum(rr), s3 = warp_sum(rr * rr);
    float s4 = warp_sum(f),  s5 = warp_sum(f * f);
    if (lane == 0) {
        atomicAdd(&g_stats[0], s0); atomicAdd(&g_stats[1], s1);
        atomicAdd(&g_stats[2], s2); atomicAdd(&g_stats[3], s3);
        atomicAdd(&g_stats[4], s4); atomicAdd(&g_stats[5], s5);
    }
}

// ---------------- BN + relu + conv1d(3->1) -> g_q ----------------
__global__ __launch_bounds__(256) void k_q(const float* __restrict__ hT,
                                           const float* __restrict__ rel_emb,
                                           const float* __restrict__ freq,
                                           const void* sidx, const void* ridx,
                                           const float* __restrict__ bng, const float* __restrict__ bnb,
                                           const float* __restrict__ cw,  const float* __restrict__ cb) {
    int idx = blockIdx.x * blockDim.x + threadIdx.x;
    if (idx >= BATCH * HDIM) return;
    int b = idx / HDIM, h = idx % HDIM;
    int is64 = g_is64;
    long long s = ld_idx(sidx, b, is64);
    long long r = ld_idx(ridx, b, is64);
    const float inv = 1.0f / (float)(BATCH * HDIM);
    float m0 = g_stats[0] * inv, m1 = g_stats[2] * inv, m2 = g_stats[4] * inv;
    float v0 = g_stats[1] * inv - m0 * m0;
    float v1 = g_stats[3] * inv - m1 * m1;
    float v2 = g_stats[5] * inv - m2 * m2;
    float rs0 = rsqrtf(v0 + BN_EPS), rs1 = rsqrtf(v1 + BN_EPS), rs2 = rsqrtf(v2 + BN_EPS);
    float x0 = hT[(long long)h * NUM_E + s];
    float x1 = rel_emb[r * HDIM + h];
    float x2 = freq[idx];
    float y0 = fmaxf((x0 - m0) * rs0 * bng[0] + bnb[0], 0.f);
    float y1 = fmaxf((x1 - m1) * rs1 * bng[1] + bnb[1], 0.f);
    float y2 = fmaxf((x2 - m2) * rs2 * bng[2] + bnb[2], 0.f);
    g_q[idx] = y0 * cw[0] + y1 * cw[1] + y2 * cw[2] + cb[0];
}

// ---------------- scores part 1: rows b in [200,512) — standard tiled GEMM ----------------
// Reads hT (= out rows 0..199) freely; writes only rows >= 200 -> no hazard.
// Tile 64b x 64n, BK=20, ~10.7KB smem -> 4+ blocks/SM. Microtile 2b x 8n.
__global__ __launch_bounds__(256, 4) void k_scores_hi(float* __restrict__ out) {
    __shared__ float qs[20][68];   // [k][bi], padded
    __shared__ float hs[20][64];   // [k][j]

    const float* hT = out;         // rows 0..199
    const long long n0 = (long long)blockIdx.x * 64;
    const int b0 = 200 + blockIdx.y * 64;          // 200..456 (5 y-blocks, covers 200..519, masked)
    const int t = threadIdx.x;
    const int tx = t & 7;          // n-group of 8
    const int ty = t >> 3;         // b-group of 2
    const int jmax = (NUM_E - n0 >= 64) ? 64 : (int)(NUM_E - n0);

    float acc[2][8];
    #pragma unroll
    for (int a = 0; a < 2; a++)
        #pragma unroll
        for (int j = 0; j < 8; j++) acc[a][j] = 0.f;

    for (int kt = 0; kt < 10; ++kt) {
        __syncthreads();
        for (int i = t; i < 64 * 20; i += 256) {     // q tile: 5 per thread
            int bi = i / 20, kk = i % 20;
            int b = b0 + bi;
            qs[kk][bi] = (b < BATCH) ? g_q[b * HDIM + kt * 20 + kk] : 0.f;
        }
        for (int i = t; i < 20 * 64; i += 256) {     // h tile: 5 per thread
            int kk = i / 64, j = i % 64;
            hs[kk][j] = (j < jmax) ? hT[(long long)(kt * 20 + kk) * NUM_E + n0 + j] : 0.f;
        }
        __syncthreads();

        #pragma unroll
        for (int kk = 0; kk < 20; ++kk) {
            float4 h0 = *(float4*)&hs[kk][tx * 8];
            float4 h1 = *(float4*)&hs[kk][tx * 8 + 4];
            float q0 = qs[kk][ty * 2];
            float q1 = qs[kk][ty * 2 + 1];
            acc[0][0] += q0 * h0.x; acc[0][1] += q0 * h0.y; acc[0][2] += q0 * h0.z; acc[0][3] += q0 * h0.w;
            acc[0][4] += q0 * h1.x; acc[0][5] += q0 * h1.y; acc[0][6] += q0 * h1.z; acc[0][7] += q0 * h1.w;
            acc[1][0] += q1 * h0.x; acc[1][1] += q1 * h0.y; acc[1][2] += q1 * h0.z; acc[1][3] += q1 * h0.w;
            acc[1][4] += q1 * h1.x; acc[1][5] += q1 * h1.y; acc[1][6] += q1 * h1.z; acc[1][7] += q1 * h1.w;
        }
    }

    if (n0 + tx * 8 + 7 < NUM_E) {   // NUM_E % 8 == 0 -> whole group in or out
        #pragma unroll
        for (int a = 0; a < 2; ++a) {
            long long b = b0 + ty * 2 + a;
            if (b < BATCH) {
                *(float4*)(out + b * NUM_E + n0 + tx * 8)     = make_float4(acc[a][0], acc[a][1], acc[a][2], acc[a][3]);
                *(float4*)(out + b * NUM_E + n0 + tx * 8 + 4) = make_float4(acc[a][4], acc[a][5], acc[a][6], acc[a][7]);
            }
        }
    }
}

// ---------------- scores part 2: rows b in [0,200) — panel-exclusive, overwrites hT ----------
// Block owns a 64-col panel: stages hT[:,panel] into smem FIRST, then writes out[:,panel].
__global__ __launch_bounds__(256, 2) void k_scores_lo(float* __restrict__ out) {
    extern __shared__ float smem[];
    float* h_sm = smem;              // [k][j] : 200 x 64
    float* q_sm = smem + HDIM * 64;  // [bi][k]: 64 x 204

    const int t = threadIdx.x;
    const long long n0 = (long long)blockIdx.x * 64;
    const int jmax = (NUM_E - n0 >= 64) ? 64 : (int)(NUM_E - n0);

    for (int i = t; i < HDIM * 16; i += 256) {
        int c = i / 16, j4 = i % 16;
        float4 v = make_float4(0.f, 0.f, 0.f, 0.f);
        if (j4 * 4 < jmax)
            v = *(const float4*)(out + (long long)c * NUM_E + n0 + j4 * 4);
        *(float4*)&h_sm[c * 64 + j4 * 4] = v;
    }

    const int tx = t & 15;   // n-group of 4
    const int ty = t >> 4;   // b-group of 4
    const bool ncheck = (n0 + tx * 4 + 3) < NUM_E;

    for (int bc = 0; bc < 4; ++bc) {                 // b chunks 0..255, stores masked to b<200
        const int b0 = bc * 64;
        __syncthreads();
        for (int i = t; i < 64 * 50; i += 256) {
            int bi = i / 50, k4 = i % 50;
            float4 v = *(const float4*)(g_q + (b0 + bi) * HDIM + k4 * 4);
            *(float4*)&q_sm[bi * 204 + k4 * 4] = v;
        }
        __syncthreads();

        float acc[16];
        #pragma unroll
        for (int i = 0; i < 16; i++) acc[i] = 0.f;

        for (int k4 = 0; k4 < 50; ++k4) {
            float qf[16];
            #pragma unroll
            for (int a = 0; a < 4; ++a) {
                float4 qv = *(float4*)&q_sm[(ty * 4 + a) * 204 + k4 * 4];
                qf[a * 4 + 0] = qv.x; qf[a * 4 + 1] = qv.y;
                qf[a * 4 + 2] = qv.z; qf[a * 4 + 3] = qv.w;
            }
            #pragma unroll
            for (int j = 0; j < 4; ++j) {
                float4 h4 = *(float4*)&h_sm[(k4 * 4 + j) * 64 + tx * 4];
                #pragma unroll
                for (int a = 0; a < 4; ++a) {
                    float qv = qf[a * 4 + j];
                    acc[a * 4 + 0] += qv * h4.x; acc[a * 4 + 1] += qv * h4.y;
                    acc[a * 4 + 2] += qv * h4.z; acc[a * 4 + 3] += qv * h4.w;
                }
            }
        }

        if (ncheck) {
            #pragma unroll
            for (int a = 0; a < 4; ++a) {
                long long b = b0 + ty * 4 + a;
                if (b < 200)
                    *(float4*)(out + b * NUM_E + n0 + tx * 4) =
                        make_float4(acc[a * 4 + 0], acc[a * 4 + 1], acc[a * 4 + 2], acc[a * 4 + 3]);
            }
        }
    }
}

// ---------------- launch ----------------
extern "C" void kernel_launch(void* const* d_in, const int* in_sizes, int n_in,
                              void* d_out, int out_size) {
    const float* ent  = (const float*)d_in[0];
    const float* rel  = (const float*)d_in[1];
    const float* Wn1  = (const float*)d_in[2];
    const float* Wl1  = (const float*)d_in[3];
    const float* Wn2  = (const float*)d_in[4];
    const float* Wl2  = (const float*)d_in[5];
    const float* gth  = (const float*)d_in[6];
    const float* gw   = (const float*)d_in[7];
    const float* gb   = (const float*)d_in[8];
    const float* bng  = (const float*)d_in[9];
    const float* bnb  = (const float*)d_in[10];
    const float* cw   = (const float*)d_in[11];
    const float* cb   = (const float*)d_in[12];
    const float* freq = (const float*)d_in[13];
    const void*  src  = d_in[14];
    const void*  dst  = d_in[15];
    const void*  etp  = d_in[16];
    const void*  sidx = d_in[17];
    const void*  ridx = d_in[18];
    float* out = (float*)d_out;

    float* h1  = out;             // [0, 20M)
    float* agg = out + AGG_OFF;   // [20M, 40M); later h2 in place
    float* hT  = out;             // [0, 20M), transposed h_final (after h1 dead)

    const int TRANS_SMEM  = (32 * HDIM * 2 + 2 * 2 * 8 * HDIM) * (int)sizeof(float);  // 76.8 KB
    const int SCORES_SMEM = (HDIM * 64 + 64 * 204) * (int)sizeof(float);              // 103.4 KB
    cudaFuncSetAttribute(k_transform, cudaFuncAttributeMaxDynamicSharedMemorySize, TRANS_SMEM);
    cudaFuncSetAttribute(k_scores_lo, cudaFuncAttributeMaxDynamicSharedMemorySize, SCORES_SMEM);

    const int zgrid = (NUM_E * H4 + 255) / 256;

    k_zero_init<<<zgrid, 256>>>(agg);
    k_detect<<<1, 32>>>((const unsigned int*)src);

    // layer 1
    k_edges<<<NEDGE / 8, 256>>>(src, dst, etp, rel, ent, agg, 1);
    k_transform<<<NUM_E / 32, 400, TRANS_SMEM>>>(ent, Wn1, Wl1, agg, h1);

    // layer 2 (h2 in place over agg)
    k_zero_agg<<<zgrid, 256>>>(agg);
    k_edges<<<NEDGE / 8, 256>>>(src, dst, etp, rel, h1, agg, 0);
    k_transform<<<NUM_E / 32, 400, TRANS_SMEM>>>(h1, Wn2, Wl2, agg, agg);

    // gate + transposed blend into hT = out[0,20M)
    k_gatepre<<<NUM_E / 8, 256>>>(gth, gw, gb);
    k_blendT<<<NUM_E / 32, 256>>>(agg /*h2*/, ent, hT);

    // ConvE head
    k_bnstats<<<BATCH, 256>>>(hT, rel, freq, sidx, ridx);
    k_q<<<(BATCH * HDIM + 255) / 256, 256>>>(hT, rel, freq, sidx, ridx, bng, bnb, cw, cb);

    // scores: rows >=200 first (reads hT, writes disjoint rows), then rows <200 in place
    dim3 hgrid((NUM_E + 63) / 64, 5);
    k_scores_hi<<<hgrid, 256>>>(out);
    k_scores_lo<<<(NUM_E + 63) / 64, 256, SCORES_SMEM>>>(out);
}

// round 12
// speedup vs baseline: 1.1599x; 1.1599x over previous
#include <cuda_runtime.h>
#include <math.h>

#define NUM_E   100000
#define HDIM    200
#define H4      50          // HDIM / 4
#define NEDGE   1000000
#define BATCH   512
#define RRELU_SLOPE 0.2291666666666667f
#define BN_EPS  1e-5f

#define AGG_OFF ((long long)NUM_E * HDIM)   // agg/h2 region starts at out + 20M floats

// ---------------- tiny device globals ONLY (~1.21 MB; no static ctor) ----------------
__device__ float g_deg  [NUM_E];
__device__ float g_gate [NUM_E];
__device__ float g_q    [BATCH * HDIM];
__device__ float g_stats[8];
__device__ int   g_is64;

// ---------------- helpers ----------------
__device__ __forceinline__ long long ld_idx(const void* p, long long i, int is64) {
    if (is64) return ((const long long*)p)[i];
    return (long long)((const int*)p)[i];
}

__device__ __forceinline__ void red_add_v4(float* addr, float4 v) {
    asm volatile("red.global.add.v4.f32 [%0], {%1,%2,%3,%4};"
                 :: "l"(addr), "f"(v.x), "f"(v.y), "f"(v.z), "f"(v.w) : "memory");
}

__device__ __forceinline__ float warp_sum(float v) {
    #pragma unroll
    for (int o = 16; o > 0; o >>= 1) v += __shfl_xor_sync(0xffffffffu, v, o);
    return v;
}

__device__ __forceinline__ float rrelu(float x) {
    return x >= 0.0f ? x : x * RRELU_SLOPE;
}

// ---------------- index width detection (int32 vs int64) ----------------
__global__ __launch_bounds__(32) void k_detect(const unsigned int* w) {
    if (threadIdx.x == 0) {
        int is64 = 1;
        for (int i = 0; i < 64; i++) {
            if (w[2 * i + 1] != 0u) { is64 = 0; break; }
        }
        g_is64 = is64;
    }
}

// ---------------- zero kernel (initial only; layer-2 re-zero is fused into transform #1) -------
__global__ __launch_bounds__(256) void k_zero_init(float* __restrict__ agg) {
    long long i = (long long)blockIdx.x * blockDim.x + threadIdx.x;
    float4 z = make_float4(0.f, 0.f, 0.f, 0.f);
    if (i < (long long)NUM_E * H4) ((float4*)agg)[i] = z;
    if (i < NUM_E / 4)             ((float4*)g_deg)[i] = z;
    if (i < 2)                     ((float4*)g_stats)[i] = z;
}

// ---------------- edge scatter (warp per edge): agg[dst] += h[src] + rel[etype] ----------------
__global__ __launch_bounds__(256) void k_edges(const void* srcp, const void* dstp, const void* etp,
                                               const float* __restrict__ rel_emb,
                                               const float* __restrict__ hsrc,
                                               float* __restrict__ agg, int do_deg) {
    long long w = ((long long)blockIdx.x * blockDim.x + threadIdx.x) >> 5;
    int lane = threadIdx.x & 31;
    if (w >= NEDGE) return;
    int is64 = g_is64;
    long long d = ld_idx(dstp, w, is64);
    long long t = ld_idx(etp, w, is64);
    long long s = ld_idx(srcp, w, is64);
    if (do_deg && lane == 0) atomicAdd(&g_deg[d], 1.0f);
    const float4* r4 = (const float4*)(rel_emb + t * HDIM);
    const float4* h4 = (const float4*)(hsrc + s * HDIM);
    float* agb = agg + d * HDIM;
    #pragma unroll
    for (int u = 0; u < 2; ++u) {
        int c = lane + u * 32;
        if (c < H4) {
            float4 v = h4[c], r = r4[c];
            v.x += r.x; v.y += r.y; v.z += r.z; v.w += r.w;
            red_add_v4(agb + 4 * c, v);
        }
    }
}

// ---------------- fused node transform: hout = rrelu((agg/max(deg,1)) @ Wn + hin @ Wl)
// 32-row tile, 400 threads, BK=8 double-buffered W (1 sync/iter). Microtile 4x4, merged acc.
// zero_src!=0: after staging, write zeros back to this block's agg rows (replaces k_zero_agg).
// In-place safe over agg (tile fully staged in smem before any write).
__global__ __launch_bounds__(400, 2) void k_transform(const float* __restrict__ hin,
                                                      const float* __restrict__ Wn,
                                                      const float* __restrict__ Wl,
                                                      float* __restrict__ agg,
                                                      float* __restrict__ hout,
                                                      int zero_src) {
    extern __shared__ float sm[];
    float* As = sm;                   // 32*200
    float* Hs = As + 32 * HDIM;       // 32*200
    float* Wb = Hs + 32 * HDIM;       // [2 buf][2 mat][8 rows][200]

    const int tid = threadIdx.x;
    const int tx = tid % 50;
    const int ty = tid / 50;          // 0..7
    const long long base = (long long)blockIdx.x * 32;

    // stage A (pre-normalized) and H tiles; optionally zero the staged agg rows
    for (int i = tid; i < 32 * H4; i += 400) {
        int r = i / H4, c4 = i % H4;
        long long n = base + r;
        float inv = 1.0f / fmaxf(g_deg[n], 1.0f);
        float4 a = *(const float4*)(agg + n * HDIM + 4 * c4);
        a.x *= inv; a.y *= inv; a.z *= inv; a.w *= inv;
        *(float4*)(As + r * HDIM + 4 * c4) = a;
        *(float4*)(Hs + r * HDIM + 4 * c4) = *(const float4*)(hin + n * HDIM + 4 * c4);
        if (zero_src)
            *(float4*)(agg + n * HDIM + 4 * c4) = make_float4(0.f, 0.f, 0.f, 0.f);
    }

    // stage W k-tile kt into buffer buf: 2 mats x 8 rows x 50 float4 = 800 f4, 2 per thread
    auto stageW = [&](int kt, int buf) {
        #pragma unroll
        for (int u = 0; u < 2; ++u) {
            int i  = tid + u * 400;
            int m  = i / 400;
            int rr = (i % 400) / 50;
            int c4 = i % 50;
            const float* W = m ? Wl : Wn;
            *(float4*)(Wb + (((buf * 2 + m) * 8 + rr) * HDIM) + 4 * c4) =
                *(const float4*)(W + (kt * 8 + rr) * HDIM + 4 * c4);
        }
    };

    stageW(0, 0);
    __syncthreads();

    float acc[16];
    #pragma unroll
    for (int i = 0; i < 16; i++) acc[i] = 0.f;

    for (int kt = 0; kt < 25; ++kt) {
        const int cur = kt & 1;
        if (kt < 24) stageW(kt + 1, cur ^ 1);   // overlaps with compute below

        const float* Wn_s = Wb + (cur * 2 + 0) * 8 * HDIM;
        const float* Wl_s = Wb + (cur * 2 + 1) * 8 * HDIM;

        #pragma unroll
        for (int kq = 0; kq < 2; ++kq) {
            const int k = kt * 8 + kq * 4;
            float av[16], hv[16];
            #pragma unroll
            for (int r = 0; r < 4; ++r) {
                float4 a = *(float4*)&As[(ty * 4 + r) * HDIM + k];
                float4 h = *(float4*)&Hs[(ty * 4 + r) * HDIM + k];
                av[r * 4 + 0] = a.x; av[r * 4 + 1] = a.y; av[r * 4 + 2] = a.z; av[r * 4 + 3] = a.w;
                hv[r * 4 + 0] = h.x; hv[r * 4 + 1] = h.y; hv[r * 4 + 2] = h.z; hv[r * 4 + 3] = h.w;
            }
            #pragma unroll
            for (int j = 0; j < 4; ++j) {
                float4 wn = *(float4*)&Wn_s[(kq * 4 + j) * HDIM + 4 * tx];
                float4 wl = *(float4*)&Wl_s[(kq * 4 + j) * HDIM + 4 * tx];
                #pragma unroll
                for (int r = 0; r < 4; ++r) {
                    float a = av[r * 4 + j];
                    float h = hv[r * 4 + j];
                    acc[r * 4 + 0] += a * wn.x + h * wl.x;
                    acc[r * 4 + 1] += a * wn.y + h * wl.y;
                    acc[r * 4 + 2] += a * wn.z + h * wl.z;
                    acc[r * 4 + 3] += a * wn.w + h * wl.w;
                }
            }
        }
        __syncthreads();
    }

    #pragma unroll
    for (int r = 0; r < 4; ++r) {
        long long n = base + ty * 4 + r;
        float4 o;
        o.x = rrelu(acc[r * 4 + 0]);
        o.y = rrelu(acc[r * 4 + 1]);
        o.z = rrelu(acc[r * 4 + 2]);
        o.w = rrelu(acc[r * 4 + 3]);
        *(float4*)(hout + n * HDIM + 4 * tx) = o;
    }
}

// ---------------- gate scalar per node ----------------
__global__ __launch_bounds__(256) void k_gatepre(const float* __restrict__ theta,
                                                 const float* __restrict__ gw,
                                                 const float* __restrict__ gb) {
    long long w = ((long long)blockIdx.x * blockDim.x + threadIdx.x) >> 5;
    int lane = threadIdx.x & 31;
    if (w >= NUM_E) return;
    const float4* t4 = (const float4*)(theta + w * HDIM);
    const float4* w4 = (const float4*)gw;
    float p = 0.f;
    #pragma unroll
    for (int u = 0; u < 2; ++u) {
        int c = lane + u * 32;
        if (c < H4) {
            float4 a = t4[c], b = w4[c];
            p += a.x * b.x + a.y * b.y + a.z * b.z + a.w * b.w;
        }
    }
    p = warp_sum(p);
    if (lane == 0) g_gate[w] = 1.0f / (1.0f + expf(-(p + gb[0])));
}

// ---------------- blend + transpose: hT[c][n] ----------------
__global__ __launch_bounds__(256) void k_blendT(const float* __restrict__ h2,
                                                const float* __restrict__ ent,
                                                float* __restrict__ hT) {
    __shared__ float sm[32 * 201];
    const int tid = threadIdx.x;
    const long long n0 = (long long)blockIdx.x * 32;

    for (int i = tid; i < 32 * H4; i += 256) {
        int r = i / H4, c4 = i % H4;
        long long n = n0 + r;
        float g = g_gate[n], og = 1.0f - g;
        float4 h = *(const float4*)(h2 + n * HDIM + 4 * c4);
        float4 e = *(const float4*)(ent + n * HDIM + 4 * c4);
        sm[r * 201 + 4 * c4 + 0] = g * h.x + og * e.x;
        sm[r * 201 + 4 * c4 + 1] = g * h.y + og * e.y;
        sm[r * 201 + 4 * c4 + 2] = g * h.z + og * e.z;
        sm[r * 201 + 4 * c4 + 3] = g * h.w + og * e.w;
    }
    __syncthreads();

    for (int i = tid; i < HDIM * 32; i += 256) {
        int r = i & 31;
        int c = i >> 5;
        hT[(long long)c * NUM_E + n0 + r] = sm[r * 201 + c];
    }
}

// ---------------- BN batch statistics ----------------
__global__ __launch_bounds__(256) void k_bnstats(const float* __restrict__ hT,
                                                 const float* __restrict__ rel_emb,
                                                 const float* __restrict__ freq,
                                                 const void* sidx, const void* ridx) {
    int b = blockIdx.x;
    int tid = threadIdx.x;
    int lane = tid & 31;
    int is64 = g_is64;
    long long s = ld_idx(sidx, b, is64);
    long long r = ld_idx(ridx, b, is64);
    float e = 0.f, rr = 0.f, f = 0.f;
    if (tid < HDIM) {
        e  = hT[(long long)tid * NUM_E + s];
        rr = rel_emb[r * HDIM + tid];
        f  = freq[(long long)b * HDIM + tid];
    }
    float s0 = warp_sum(e),  s1 = warp_sum(e * e);
    float s2 = warp_sum(rr), s3 = warp_sum(rr * rr);
    float s4 = warp_sum(f),  s5 = warp_sum(f * f);
    if (lane == 0) {
        atomicAdd(&g_stats[0], s0); atomicAdd(&g_stats[1], s1);
        atomicAdd(&g_stats[2], s2); atomicAdd(&g_stats[3], s3);
        atomicAdd(&g_stats[4], s4); atomicAdd(&g_stats[5], s5);
    }
}

// ---------------- BN + relu + conv1d(3->1) -> g_q ----------------
__global__ __launch_bounds__(256) void k_q(const float* __restrict__ hT,
                                           const float* __restrict__ rel_emb,
                                           const float* __restrict__ freq,
                                           const void* sidx, const void* ridx,
                                           const float* __restrict__ bng, const float* __restrict__ bnb,
                                           const float* __restrict__ cw,  const float* __restrict__ cb) {
    int idx = blockIdx.x * blockDim.x + threadIdx.x;
    if (idx >= BATCH * HDIM) return;
    int b = idx / HDIM, h = idx % HDIM;
    int is64 = g_is64;
    long long s = ld_idx(sidx, b, is64);
    long long r = ld_idx(ridx, b, is64);
    const float inv = 1.0f / (float)(BATCH * HDIM);
    float m0 = g_stats[0] * inv, m1 = g_stats[2] * inv, m2 = g_stats[4] * inv;
    float v0 = g_stats[1] * inv - m0 * m0;
    float v1 = g_stats[3] * inv - m1 * m1;
    float v2 = g_stats[5] * inv - m2 * m2;
    float rs0 = rsqrtf(v0 + BN_EPS), rs1 = rsqrtf(v1 + BN_EPS), rs2 = rsqrtf(v2 + BN_EPS);
    float x0 = hT[(long long)h * NUM_E + s];
    float x1 = rel_emb[r * HDIM + h];
    float x2 = freq[idx];
    float y0 = fmaxf((x0 - m0) * rs0 * bng[0] + bnb[0], 0.f);
    float y1 = fmaxf((x1 - m1) * rs1 * bng[1] + bnb[1], 0.f);
    float y2 = fmaxf((x2 - m2) * rs2 * bng[2] + bnb[2], 0.f);
    g_q[idx] = y0 * cw[0] + y1 * cw[1] + y2 * cw[2] + cb[0];
}

// ---------------- scores = q @ h_final^T, IN PLACE over hT (panel-exclusive blocks) -----------
// Block owns a 64-col panel: stages hT[:,panel] into smem, then writes out[:,panel].
// k-vectorized microtile 4x4: 8 LDS.128 per 64 FFMA. Dynamic smem 103.4KB.
__global__ __launch_bounds__(256, 2) void k_scores(float* __restrict__ out) {
    extern __shared__ float smem[];
    float* h_sm = smem;              // [k][j] : 200 x 64
    float* q_sm = smem + HDIM * 64;  // [bi][k]: 64 x 204 (padded, 16B-aligned rows)

    const int t = threadIdx.x;
    const long long n0 = (long long)blockIdx.x * 64;
    const int jmax = (NUM_E - n0 >= 64) ? 64 : (int)(NUM_E - n0);

    for (int i = t; i < HDIM * 16; i += 256) {
        int c = i / 16, j4 = i % 16;
        float4 v = make_float4(0.f, 0.f, 0.f, 0.f);
        if (j4 * 4 < jmax)
            v = *(const float4*)(out + (long long)c * NUM_E + n0 + j4 * 4);
        *(float4*)&h_sm[c * 64 + j4 * 4] = v;
    }

    const int tx = t & 15;   // n-group of 4
    const int ty = t >> 4;   // b-group of 4
    const bool do_store = (n0 + tx * 4 + 3) < NUM_E;

    for (int bc = 0; bc < BATCH / 64; ++bc) {
        const int b0 = bc * 64;
        __syncthreads();
        for (int i = t; i < 64 * 50; i += 256) {
            int bi = i / 50, k4 = i % 50;
            float4 v = *(const float4*)(g_q + (b0 + bi) * HDIM + k4 * 4);
            *(float4*)&q_sm[bi * 204 + k4 * 4] = v;
        }
        __syncthreads();

        float acc[16];
        #pragma unroll
        for (int i = 0; i < 16; i++) acc[i] = 0.f;

        for (int k4 = 0; k4 < 50; ++k4) {
            float qf[16];
            #pragma unroll
            for (int a = 0; a < 4; ++a) {
                float4 qv = *(float4*)&q_sm[(ty * 4 + a) * 204 + k4 * 4];
                qf[a * 4 + 0] = qv.x; qf[a * 4 + 1] = qv.y;
                qf[a * 4 + 2] = qv.z; qf[a * 4 + 3] = qv.w;
            }
            #pragma unroll
            for (int j = 0; j < 4; ++j) {
                float4 h4 = *(float4*)&h_sm[(k4 * 4 + j) * 64 + tx * 4];
                #pragma unroll
                for (int a = 0; a < 4; ++a) {
                    float qv = qf[a * 4 + j];
                    acc[a * 4 + 0] += qv * h4.x; acc[a * 4 + 1] += qv * h4.y;
                    acc[a * 4 + 2] += qv * h4.z; acc[a * 4 + 3] += qv * h4.w;
                }
            }
        }

        if (do_store) {
            #pragma unroll
            for (int a = 0; a < 4; ++a) {
                long long b = b0 + ty * 4 + a;
                *(float4*)(out + b * NUM_E + n0 + tx * 4) =
                    make_float4(acc[a * 4 + 0], acc[a * 4 + 1], acc[a * 4 + 2], acc[a * 4 + 3]);
            }
        }
    }
}

// ---------------- launch ----------------
extern "C" void kernel_launch(void* const* d_in, const int* in_sizes, int n_in,
                              void* d_out, int out_size) {
    const float* ent  = (const float*)d_in[0];
    const float* rel  = (const float*)d_in[1];
    const float* Wn1  = (const float*)d_in[2];
    const float* Wl1  = (const float*)d_in[3];
    const float* Wn2  = (const float*)d_in[4];
    const float* Wl2  = (const float*)d_in[5];
    const float* gth  = (const float*)d_in[6];
    const float* gw   = (const float*)d_in[7];
    const float* gb   = (const float*)d_in[8];
    const float* bng  = (const float*)d_in[9];
    const float* bnb  = (const float*)d_in[10];
    const float* cw   = (const float*)d_in[11];
    const float* cb   = (const float*)d_in[12];
    const float* freq = (const float*)d_in[13];
    const void*  src  = d_in[14];
    const void*  dst  = d_in[15];
    const void*  etp  = d_in[16];
    const void*  sidx = d_in[17];
    const void*  ridx = d_in[18];
    float* out = (float*)d_out;

    float* h1  = out;             // [0, 20M)
    float* agg = out + AGG_OFF;   // [20M, 40M); later h2 in place
    float* hT  = out;             // [0, 20M), transposed h_final (after h1 dead)

    const int TRANS_SMEM  = (32 * HDIM * 2 + 2 * 2 * 8 * HDIM) * (int)sizeof(float);  // 76.8 KB
    const int SCORES_SMEM = (HDIM * 64 + 64 * 204) * (int)sizeof(float);              // 103.4 KB
    cudaFuncSetAttribute(k_transform, cudaFuncAttributeMaxDynamicSharedMemorySize, TRANS_SMEM);
    cudaFuncSetAttribute(k_scores,    cudaFuncAttributeMaxDynamicSharedMemorySize, SCORES_SMEM);

    const int zgrid = (NUM_E * H4 + 255) / 256;

    k_zero_init<<<zgrid, 256>>>(agg);
    k_detect<<<1, 32>>>((const unsigned int*)src);

    // layer 1 (transform #1 also re-zeroes agg for layer 2)
    k_edges<<<NEDGE / 8, 256>>>(src, dst, etp, rel, ent, agg, 1);
    k_transform<<<NUM_E / 32, 400, TRANS_SMEM>>>(ent, Wn1, Wl1, agg, h1, 1);

    // layer 2 (h2 in place over agg)
    k_edges<<<NEDGE / 8, 256>>>(src, dst, etp, rel, h1, agg, 0);
    k_transform<<<NUM_E / 32, 400, TRANS_SMEM>>>(h1, Wn2, Wl2, agg, agg, 0);

    // gate + transposed blend into hT = out[0,20M)
    k_gatepre<<<NUM_E / 8, 256>>>(gth, gw, gb);
    k_blendT<<<NUM_E / 32, 256>>>(agg /*h2*/, ent, hT);

    // ConvE head
    k_bnstats<<<BATCH, 256>>>(hT, rel, freq, sidx, ridx);
    k_q<<<(BATCH * HDIM + 255) / 256, 256>>>(hT, rel, freq, sidx, ridx, bng, bnb, cw, cb);

    // scores in place over the whole output (panel-exclusive blocks)
    k_scores<<<(NUM_E + 63) / 64, 256, SCORES_SMEM>>>(out);
}

// round 13
// speedup vs baseline: 1.2540x; 1.0812x over previous
#include <cuda_runtime.h>
#include <math.h>

#define NUM_E   100000
#define HDIM    200
#define H4      50          // HDIM / 4
#define NEDGE   1000000
#define BATCH   512
#define RRELU_SLOPE 0.2291666666666667f
#define BN_EPS  1e-5f

#define AGG_OFF ((long long)NUM_E * HDIM)   // agg/h2 region starts at out + 20M floats

// ---------------- tiny device globals ONLY (~1.21 MB; no static ctor) ----------------
__device__ float g_deg  [NUM_E];
__device__ float g_gate [NUM_E];
__device__ float g_q    [BATCH * HDIM];
__device__ float g_stats[8];
__device__ int   g_is64;

// ---------------- helpers ----------------
__device__ __forceinline__ long long ld_idx(const void* p, long long i, int is64) {
    if (is64) return ((const long long*)p)[i];
    return (long long)((const int*)p)[i];
}

__device__ __forceinline__ void red_add_v4(float* addr, float4 v) {
    asm volatile("red.global.add.v4.f32 [%0], {%1,%2,%3,%4};"
                 :: "l"(addr), "f"(v.x), "f"(v.y), "f"(v.z), "f"(v.w) : "memory");
}

__device__ __forceinline__ float warp_sum(float v) {
    #pragma unroll
    for (int o = 16; o > 0; o >>= 1) v += __shfl_xor_sync(0xffffffffu, v, o);
    return v;
}

__device__ __forceinline__ float rrelu(float x) {
    return x >= 0.0f ? x : x * RRELU_SLOPE;
}

// ---------------- index width detection (int32 vs int64) ----------------
__global__ __launch_bounds__(32) void k_detect(const unsigned int* w) {
    if (threadIdx.x == 0) {
        int is64 = 1;
        for (int i = 0; i < 64; i++) {
            if (w[2 * i + 1] != 0u) { is64 = 0; break; }
        }
        g_is64 = is64;
    }
}

// ---------------- zero kernels ----------------
__global__ __launch_bounds__(256) void k_zero_init(float* __restrict__ agg) {
    long long i = (long long)blockIdx.x * blockDim.x + threadIdx.x;
    float4 z = make_float4(0.f, 0.f, 0.f, 0.f);
    if (i < (long long)NUM_E * H4) ((float4*)agg)[i] = z;
    if (i < NUM_E / 4)             ((float4*)g_deg)[i] = z;
    if (i < 2)                     ((float4*)g_stats)[i] = z;
}

__global__ __launch_bounds__(256) void k_zero_agg(float* __restrict__ agg) {
    long long i = (long long)blockIdx.x * blockDim.x + threadIdx.x;
    if (i < (long long)NUM_E * H4)
        ((float4*)agg)[i] = make_float4(0.f, 0.f, 0.f, 0.f);
}

// ---------------- edge scatter (warp per edge): agg[dst] += h[src] + rel[etype] ----------------
__global__ __launch_bounds__(256) void k_edges(const void* srcp, const void* dstp, const void* etp,
                                               const float* __restrict__ rel_emb,
                                               const float* __restrict__ hsrc,
                                               float* __restrict__ agg, int do_deg) {
    long long w = ((long long)blockIdx.x * blockDim.x + threadIdx.x) >> 5;
    int lane = threadIdx.x & 31;
    if (w >= NEDGE) return;
    int is64 = g_is64;
    long long d = ld_idx(dstp, w, is64);
    long long t = ld_idx(etp, w, is64);
    long long s = ld_idx(srcp, w, is64);
    if (do_deg && lane == 0) atomicAdd(&g_deg[d], 1.0f);
    const float4* r4 = (const float4*)(rel_emb + t * HDIM);
    const float4* h4 = (const float4*)(hsrc + s * HDIM);
    float* agb = agg + d * HDIM;
    #pragma unroll
    for (int u = 0; u < 2; ++u) {
        int c = lane + u * 32;
        if (c < H4) {
            float4 v = h4[c], r = r4[c];
            v.x += r.x; v.y += r.y; v.z += r.z; v.w += r.w;
            red_add_v4(agb + 4 * c, v);
        }
    }
}

// ---------------- fused node transform: hout = rrelu((agg/max(deg,1)) @ Wn + hin @ Wl)
// 32-row tile, 400 threads, BK=8 double-buffered W (1 sync/iter). Microtile 4x4, merged acc.
// In-place safe over agg (tile fully staged in smem before any write). [R11-proven: 681us]
__global__ __launch_bounds__(400, 2) void k_transform(const float* __restrict__ hin,
                                                      const float* __restrict__ Wn,
                                                      const float* __restrict__ Wl,
                                                      const float* __restrict__ agg,
                                                      float* __restrict__ hout) {
    extern __shared__ float sm[];
    float* As = sm;                   // 32*200
    float* Hs = As + 32 * HDIM;       // 32*200
    float* Wb = Hs + 32 * HDIM;       // [2 buf][2 mat][8 rows][200]

    const int tid = threadIdx.x;
    const int tx = tid % 50;
    const int ty = tid / 50;          // 0..7
    const long long base = (long long)blockIdx.x * 32;

    // stage A (pre-normalized) and H tiles
    for (int i = tid; i < 32 * H4; i += 400) {
        int r = i / H4, c4 = i % H4;
        long long n = base + r;
        float inv = 1.0f / fmaxf(g_deg[n], 1.0f);
        float4 a = *(const float4*)(agg + n * HDIM + 4 * c4);
        a.x *= inv; a.y *= inv; a.z *= inv; a.w *= inv;
        *(float4*)(As + r * HDIM + 4 * c4) = a;
        *(float4*)(Hs + r * HDIM + 4 * c4) = *(const float4*)(hin + n * HDIM + 4 * c4);
    }

    // stage W k-tile kt into buffer buf: 2 mats x 8 rows x 50 float4 = 800 f4, 2 per thread
    auto stageW = [&](int kt, int buf) {
        #pragma unroll
        for (int u = 0; u < 2; ++u) {
            int i  = tid + u * 400;
            int m  = i / 400;
            int rr = (i % 400) / 50;
            int c4 = i % 50;
            const float* W = m ? Wl : Wn;
            *(float4*)(Wb + (((buf * 2 + m) * 8 + rr) * HDIM) + 4 * c4) =
                *(const float4*)(W + (kt * 8 + rr) * HDIM + 4 * c4);
        }
    };

    stageW(0, 0);
    __syncthreads();

    float acc[16];
    #pragma unroll
    for (int i = 0; i < 16; i++) acc[i] = 0.f;

    for (int kt = 0; kt < 25; ++kt) {
        const int cur = kt & 1;
        if (kt < 24) stageW(kt + 1, cur ^ 1);   // overlaps with compute below

        const float* Wn_s = Wb + (cur * 2 + 0) * 8 * HDIM;
        const float* Wl_s = Wb + (cur * 2 + 1) * 8 * HDIM;

        #pragma unroll
        for (int kq = 0; kq < 2; ++kq) {
            const int k = kt * 8 + kq * 4;
            float av[16], hv[16];
            #pragma unroll
            for (int r = 0; r < 4; ++r) {
                float4 a = *(float4*)&As[(ty * 4 + r) * HDIM + k];
                float4 h = *(float4*)&Hs[(ty * 4 + r) * HDIM + k];
                av[r * 4 + 0] = a.x; av[r * 4 + 1] = a.y; av[r * 4 + 2] = a.z; av[r * 4 + 3] = a.w;
                hv[r * 4 + 0] = h.x; hv[r * 4 + 1] = h.y; hv[r * 4 + 2] = h.z; hv[r * 4 + 3] = h.w;
            }
            #pragma unroll
            for (int j = 0; j < 4; ++j) {
                float4 wn = *(float4*)&Wn_s[(kq * 4 + j) * HDIM + 4 * tx];
                float4 wl = *(float4*)&Wl_s[(kq * 4 + j) * HDIM + 4 * tx];
                #pragma unroll
                for (int r = 0; r < 4; ++r) {
                    float a = av[r * 4 + j];
                    float h = hv[r * 4 + j];
                    acc[r * 4 + 0] += a * wn.x + h * wl.x;
                    acc[r * 4 + 1] += a * wn.y + h * wl.y;
                    acc[r * 4 + 2] += a * wn.z + h * wl.z;
                    acc[r * 4 + 3] += a * wn.w + h * wl.w;
                }
            }
        }
        __syncthreads();
    }

    #pragma unroll
    for (int r = 0; r < 4; ++r) {
        long long n = base + ty * 4 + r;
        float4 o;
        o.x = rrelu(acc[r * 4 + 0]);
        o.y = rrelu(acc[r * 4 + 1]);
        o.z = rrelu(acc[r * 4 + 2]);
        o.w = rrelu(acc[r * 4 + 3]);
        *(float4*)(hout + n * HDIM + 4 * tx) = o;
    }
}

// ---------------- gate scalar per node ----------------
__global__ __launch_bounds__(256) void k_gatepre(const float* __restrict__ theta,
                                                 const float* __restrict__ gw,
                                                 const float* __restrict__ gb) {
    long long w = ((long long)blockIdx.x * blockDim.x + threadIdx.x) >> 5;
    int lane = threadIdx.x & 31;
    if (w >= NUM_E) return;
    const float4* t4 = (const float4*)(theta + w * HDIM);
    const float4* w4 = (const float4*)gw;
    float p = 0.f;
    #pragma unroll
    for (int u = 0; u < 2; ++u) {
        int c = lane + u * 32;
        if (c < H4) {
            float4 a = t4[c], b = w4[c];
            p += a.x * b.x + a.y * b.y + a.z * b.z + a.w * b.w;
        }
    }
    p = warp_sum(p);
    if (lane == 0) g_gate[w] = 1.0f / (1.0f + expf(-(p + gb[0])));
}

// ---------------- blend + transpose: hT[c][n] ----------------
__global__ __launch_bounds__(256) void k_blendT(const float* __restrict__ h2,
                                                const float* __restrict__ ent,
                                                float* __restrict__ hT) {
    __shared__ float sm[32 * 201];
    const int tid = threadIdx.x;
    const long long n0 = (long long)blockIdx.x * 32;

    for (int i = tid; i < 32 * H4; i += 256) {
        int r = i / H4, c4 = i % H4;
        long long n = n0 + r;
        float g = g_gate[n], og = 1.0f - g;
        float4 h = *(const float4*)(h2 + n * HDIM + 4 * c4);
        float4 e = *(const float4*)(ent + n * HDIM + 4 * c4);
        sm[r * 201 + 4 * c4 + 0] = g * h.x + og * e.x;
        sm[r * 201 + 4 * c4 + 1] = g * h.y + og * e.y;
        sm[r * 201 + 4 * c4 + 2] = g * h.z + og * e.z;
        sm[r * 201 + 4 * c4 + 3] = g * h.w + og * e.w;
    }
    __syncthreads();

    for (int i = tid; i < HDIM * 32; i += 256) {
        int r = i & 31;
        int c = i >> 5;
        hT[(long long)c * NUM_E + n0 + r] = sm[r * 201 + c];
    }
}

// ---------------- BN batch statistics ----------------
__global__ __launch_bounds__(256) void k_bnstats(const float* __restrict__ hT,
                                                 const float* __restrict__ rel_emb,
                                                 const float* __restrict__ freq,
                                                 const void* sidx, const void* ridx) {
    int b = blockIdx.x;
    int tid = threadIdx.x;
    int lane = tid & 31;
    int is64 = g_is64;
    long long s = ld_idx(sidx, b, is64);
    long long r = ld_idx(ridx, b, is64);
    float e = 0.f, rr = 0.f, f = 0.f;
    if (tid < HDIM) {
        e  = hT[(long long)tid * NUM_E + s];
        rr = rel_emb[r * HDIM + tid];
        f  = freq[(long long)b * HDIM + tid];
    }
    float s0 = warp_sum(e),  s1 = warp_sum(e * e);
    float s2 = warp_sum(rr), s3 = warp_sum(rr * rr);
    float s4 = warp_sum(f),  s5 = warp_sum(f * f);
    if (lane == 0) {
        atomicAdd(&g_stats[0], s0); atomicAdd(&g_stats[1], s1);
        atomicAdd(&g_stats[2], s2); atomicAdd(&g_stats[3], s3);
        atomicAdd(&g_stats[4], s4); atomicAdd(&g_stats[5], s5);
    }
}

// ---------------- BN + relu + conv1d(3->1) -> g_q ----------------
__global__ __launch_bounds__(256) void k_q(const float* __restrict__ hT,
                                           const float* __restrict__ rel_emb,
                                           const float* __restrict__ freq,
                                           const void* sidx, const void* ridx,
                                           const float* __restrict__ bng, const float* __restrict__ bnb,
                                           const float* __restrict__ cw,  const float* __restrict__ cb) {
    int idx = blockIdx.x * blockDim.x + threadIdx.x;
    if (idx >= BATCH * HDIM) return;
    int b = idx / HDIM, h = idx % HDIM;
    int is64 = g_is64;
    long long s = ld_idx(sidx, b, is64);
    long long r = ld_idx(ridx, b, is64);
    const float inv = 1.0f / (float)(BATCH * HDIM);
    float m0 = g_stats[0] * inv, m1 = g_stats[2] * inv, m2 = g_stats[4] * inv;
    float v0 = g_stats[1] * inv - m0 * m0;
    float v1 = g_stats[3] * inv - m1 * m1;
    float v2 = g_stats[5] * inv - m2 * m2;
    float rs0 = rsqrtf(v0 + BN_EPS), rs1 = rsqrtf(v1 + BN_EPS), rs2 = rsqrtf(v2 + BN_EPS);
    float x0 = hT[(long long)h * NUM_E + s];
    float x1 = rel_emb[r * HDIM + h];
    float x2 = freq[idx];
    float y0 = fmaxf((x0 - m0) * rs0 * bng[0] + bnb[0], 0.f);
    float y1 = fmaxf((x1 - m1) * rs1 * bng[1] + bnb[1], 0.f);
    float y2 = fmaxf((x2 - m2) * rs2 * bng[2] + bnb[2], 0.f);
    g_q[idx] = y0 * cw[0] + y1 * cw[1] + y2 * cw[2] + cb[0];
}

// ---------------- scores = q @ h_final^T, IN PLACE over hT (panel-exclusive blocks) -----------
// Block owns a 64-col panel: stages hT[:,panel] into smem, then writes out[:,panel].
// k-vectorized microtile 4x4: 8 LDS.128 per 64 FFMA. Dynamic smem 103.4KB. [R10-proven]
__global__ __launch_bounds__(256, 2) void k_scores(float* __restrict__ out) {
    extern __shared__ float smem[];
    float* h_sm = smem;              // [k][j] : 200 x 64
    float* q_sm = smem + HDIM * 64;  // [bi][k]: 64 x 204 (padded, 16B-aligned rows)

    const int t = threadIdx.x;
    const long long n0 = (long long)blockIdx.x * 64;
    const int jmax = (NUM_E - n0 >= 64) ? 64 : (int)(NUM_E - n0);

    for (int i = t; i < HDIM * 16; i += 256) {
        int c = i / 16, j4 = i % 16;
        float4 v = make_float4(0.f, 0.f, 0.f, 0.f);
        if (j4 * 4 < jmax)
            v = *(const float4*)(out + (long long)c * NUM_E + n0 + j4 * 4);
        *(float4*)&h_sm[c * 64 + j4 * 4] = v;
    }

    const int tx = t & 15;   // n-group of 4
    const int ty = t >> 4;   // b-group of 4
    const bool do_store = (n0 + tx * 4 + 3) < NUM_E;

    for (int bc = 0; bc < BATCH / 64; ++bc) {
        const int b0 = bc * 64;
        __syncthreads();
        for (int i = t; i < 64 * 50; i += 256) {
            int bi = i / 50, k4 = i % 50;
            float4 v = *(const float4*)(g_q + (b0 + bi) * HDIM + k4 * 4);
            *(float4*)&q_sm[bi * 204 + k4 * 4] = v;
        }
        __syncthreads();

        float acc[16];
        #pragma unroll
        for (int i = 0; i < 16; i++) acc[i] = 0.f;

        for (int k4 = 0; k4 < 50; ++k4) {
            float qf[16];
            #pragma unroll
            for (int a = 0; a < 4; ++a) {
                float4 qv = *(float4*)&q_sm[(ty * 4 + a) * 204 + k4 * 4];
                qf[a * 4 + 0] = qv.x; qf[a * 4 + 1] = qv.y;
                qf[a * 4 + 2] = qv.z; qf[a * 4 + 3] = qv.w;
            }
            #pragma unroll
            for (int j = 0; j < 4; ++j) {
                float4 h4 = *(float4*)&h_sm[(k4 * 4 + j) * 64 + tx * 4];
                #pragma unroll
                for (int a = 0; a < 4; ++a) {
                    float qv = qf[a * 4 + j];
                    acc[a * 4 + 0] += qv * h4.x; acc[a * 4 + 1] += qv * h4.y;
                    acc[a * 4 + 2] += qv * h4.z; acc[a * 4 + 3] += qv * h4.w;
                }
            }
        }

        if (do_store) {
            #pragma unroll
            for (int a = 0; a < 4; ++a) {
                long long b = b0 + ty * 4 + a;
                *(float4*)(out + b * NUM_E + n0 + tx * 4) =
                    make_float4(acc[a * 4 + 0], acc[a * 4 + 1], acc[a * 4 + 2], acc[a * 4 + 3]);
            }
        }
    }
}

// ---------------- launch ----------------
extern "C" void kernel_launch(void* const* d_in, const int* in_sizes, int n_in,
                              void* d_out, int out_size) {
    const float* ent  = (const float*)d_in[0];
    const float* rel  = (const float*)d_in[1];
    const float* Wn1  = (const float*)d_in[2];
    const float* Wl1  = (const float*)d_in[3];
    const float* Wn2  = (const float*)d_in[4];
    const float* Wl2  = (const float*)d_in[5];
    const float* gth  = (const float*)d_in[6];
    const float* gw   = (const float*)d_in[7];
    const float* gb   = (const float*)d_in[8];
    const float* bng  = (const float*)d_in[9];
    const float* bnb  = (const float*)d_in[10];
    const float* cw   = (const float*)d_in[11];
    const float* cb   = (const float*)d_in[12];
    const float* freq = (const float*)d_in[13];
    const void*  src  = d_in[14];
    const void*  dst  = d_in[15];
    const void*  etp  = d_in[16];
    const void*  sidx = d_in[17];
    const void*  ridx = d_in[18];
    float* out = (float*)d_out;

    float* h1  = out;             // [0, 20M)
    float* agg = out + AGG_OFF;   // [20M, 40M); later h2 in place
    float* hT  = out;             // [0, 20M), transposed h_final (after h1 dead)

    const int TRANS_SMEM  = (32 * HDIM * 2 + 2 * 2 * 8 * HDIM) * (int)sizeof(float);  // 76.8 KB
    const int SCORES_SMEM = (HDIM * 64 + 64 * 204) * (int)sizeof(float);              // 103.4 KB
    cudaFuncSetAttribute(k_transform, cudaFuncAttributeMaxDynamicSharedMemorySize, TRANS_SMEM);
    cudaFuncSetAttribute(k_scores,    cudaFuncAttributeMaxDynamicSharedMemorySize, SCORES_SMEM);

    const int zgrid = (NUM_E * H4 + 255) / 256;

    k_zero_init<<<zgrid, 256>>>(agg);
    k_detect<<<1, 32>>>((const unsigned int*)src);

    // layer 1
    k_edges<<<NEDGE / 8, 256>>>(src, dst, etp, rel, ent, agg, 1);
    k_transform<<<NUM_E / 32, 400, TRANS_SMEM>>>(ent, Wn1, Wl1, agg, h1);

    // layer 2 (h2 in place over agg)
    k_zero_agg<<<zgrid, 256>>>(agg);
    k_edges<<<NEDGE / 8, 256>>>(src, dst, etp, rel, h1, agg, 0);
    k_transform<<<NUM_E / 32, 400, TRANS_SMEM>>>(h1, Wn2, Wl2, agg, agg);

    // gate + transposed blend into hT = out[0,20M)
    k_gatepre<<<NUM_E / 8, 256>>>(gth, gw, gb);
    k_blendT<<<NUM_E / 32, 256>>>(agg /*h2*/, ent, hT);

    // ConvE head
    k_bnstats<<<BATCH, 256>>>(hT, rel, freq, sidx, ridx);
    k_q<<<(BATCH * HDIM + 255) / 256, 256>>>(hT, rel, freq, sidx, ridx, bng, bnb, cw, cb);

    // scores in place over the whole output (panel-exclusive blocks)
    k_scores<<<(NUM_E + 63) / 64, 256, SCORES_SMEM>>>(out);
}